// round 7
// baseline (speedup 1.0000x reference)
#include <cuda_runtime.h>
#include <cstdint>
#include <cstring>

#define NN   50000
#define DEG  16
#define FDIM 64
#define NE   (NN * DEG)

// Scratch (allocation-free rule)
__device__ __align__(16) float g_T[NN * FDIM];
__device__ __align__(16) float g_BX[NN * FDIM * 2];  // per node: [B row (64f)][x row (64f)]
__device__ __align__(16) float g_xn[NN * FDIM];      // x_new
__device__ __align__(16) int   g_nbr[NE];
__device__ int g_is32 = 0;

// ---- packed f32x2 helpers (Blackwell) -------------------------------------
__device__ __forceinline__ unsigned long long pack2(float v) {
    unsigned long long r;
    asm("mov.b64 %0, {%1, %1};" : "=l"(r) : "f"(v));
    return r;
}
__device__ __forceinline__ void fma2(unsigned long long& d,
                                     unsigned long long a, unsigned long long b) {
    asm("fma.rn.f32x2 %0, %1, %2, %0;" : "+l"(d) : "l"(a), "l"(b));
}
__device__ __forceinline__ float2 unpack2(unsigned long long v) {
    float2 f;
    asm("mov.b64 {%0, %1}, %2;" : "=f"(f.x), "=f"(f.y) : "l"(v));
    return f;
}
__device__ __forceinline__ float sigmoid_fast(float z) {
    float t;
    asm("tanh.approx.f32 %0, %1;" : "=f"(t) : "f"(0.5f * z));
    return fmaf(0.5f, t, 0.5f);
}

// ---------------------------------------------------------------------------
// K0: dtype sniff + convert (int64 lo-words vs int32)
// ---------------------------------------------------------------------------
__global__ void k_detect(const int* __restrict__ raw)
{
    int i = (blockIdx.x * blockDim.x + threadIdx.x) * 2 + 1;
    const int lim = NE < (1 << 18) ? NE : (1 << 18);
    for (; i < lim; i += gridDim.x * blockDim.x * 2)
        if (raw[i] != 0) { atomicExch(&g_is32, 1); return; }
}
__global__ void k_convert(const int* __restrict__ raw)
{
    const int is32 = g_is32;
    for (int i = blockIdx.x * blockDim.x + threadIdx.x; i < NE;
         i += gridDim.x * blockDim.x)
        g_nbr[i] = is32 ? raw[i] : raw[2 * i];
}

// ---------------------------------------------------------------------------
// K1: T = x@wm_top; g_BX[n] = {x@wm_bot row, x row} interleaved (512B/node).
// 8 rows/warp amortized weights, f32x2 FMA.
// ---------------------------------------------------------------------------
__global__ __launch_bounds__(256, 2)
void k_gemm_tb(const float* __restrict__ x, const float* __restrict__ wm)
{
    __shared__ float2 sT[FDIM * 32];
    __shared__ float2 sB[FDIM * 32];
    __shared__ float  sx[8][8][FDIM];     // [warp][row][k]

    const int tid = threadIdx.x;
    const float2* wm2 = (const float2*)wm;
    for (int i = tid; i < FDIM * 32; i += blockDim.x) {
        sT[i] = wm2[i];
        sB[i] = wm2[FDIM * 32 + i];
    }
    __syncthreads();

    const int lane = tid & 31, wsub = tid >> 5;
    const int gw = blockIdx.x * 8 + wsub;
    const int nwarps = gridDim.x * 8;
    const float2* x2 = (const float2*)x;

    for (int c = gw; c < NN / 8; c += nwarps) {
        const int base = c * 8;
        #pragma unroll
        for (int r = 0; r < 8; r++)
            ((float2*)sx[wsub][r])[lane] = x2[(base + r) * 32 + lane];
        __syncwarp();

        unsigned long long tA[8], bA[8];
        #pragma unroll
        for (int r = 0; r < 8; r++) { tA[r] = 0ull; bA[r] = 0ull; }

        #pragma unroll 8
        for (int k = 0; k < FDIM; k++) {
            unsigned long long wt, wb;
            memcpy(&wt, &sT[k * 32 + lane], 8);
            memcpy(&wb, &sB[k * 32 + lane], 8);
            #pragma unroll
            for (int r = 0; r < 8; r++) {
                const unsigned long long xk = pack2(sx[wsub][r][k]);
                fma2(tA[r], xk, wt);
                fma2(bA[r], xk, wb);
            }
        }
        #pragma unroll
        for (int r = 0; r < 8; r++) {
            ((float2*)g_T)[(base + r) * 32 + lane] = unpack2(tA[r]);
            // interleaved record: B row then x row
            ((float2*)g_BX)[(base + r) * 64 + lane]      = unpack2(bA[r]);
            ((float2*)g_BX)[(base + r) * 64 + 32 + lane] =
                ((float2*)sx[wsub][r])[lane];
        }
        __syncwarp();
    }
}

// ---------------------------------------------------------------------------
// K2: x_new[n] = x[n] + sum_d sigmoid(T[n]+B[j])*drop[n,d]*x[j]
// Half-warp per node, float4 lanes. 3 CTAs/SM for gather-latency cover.
// B and x for neighbor j come from one contiguous 512B g_BX record.
// ---------------------------------------------------------------------------
__global__ __launch_bounds__(256, 3)
void k_edge(const float* __restrict__ x, const float* __restrict__ drop)
{
    const int tid  = threadIdx.x;
    const int lane = tid & 31;
    const int hl   = lane >> 4;          // which node of the pair
    const int fl   = lane & 15;          // float4 slot
    const int gw   = blockIdx.x * 8 + (tid >> 5);
    const int nwarps = gridDim.x * 8;

    const float4* x4  = (const float4*)x;
    const float4* BX4 = (const float4*)g_BX;
    const float4* T4  = (const float4*)g_T;

    for (int c = gw; c < NN / 2; c += nwarps) {
        const int n = c * 2 + hl;
        const float4 t = T4[n * 16 + fl];
        float4 a = x4[n * 16 + fl];

        int js[DEG];
        {
            const int4* nb4 = (const int4*)(g_nbr + n * DEG);
            #pragma unroll
            for (int q = 0; q < 4; q++) *(int4*)&js[q * 4] = nb4[q];
        }
        const float4* dm = (const float4*)(drop + (size_t)n * DEG * FDIM);

        #pragma unroll
        for (int d = 0; d < DEG; d++) {
            const int j = js[d];
            const float4 b  = BX4[j * 32 + fl];        // B half of record
            const float4 xj = BX4[j * 32 + 16 + fl];   // x half of record
            const float4 m  = __ldcs(dm + d * 16 + fl);
            a.x += sigmoid_fast(t.x + b.x) * m.x * xj.x;
            a.y += sigmoid_fast(t.y + b.y) * m.y * xj.y;
            a.z += sigmoid_fast(t.z + b.z) * m.z * xj.z;
            a.w += sigmoid_fast(t.w + b.w) * m.w * xj.w;
        }
        ((float4*)g_xn)[n * 16 + fl] = a;
    }
}

// ---------------------------------------------------------------------------
// K34 (fused): agg[n] = sum_d adj[n,d]*x_new[nbr[n,d]] staged into shared,
// then out = agg @ weight_0 + bias   (8 rows/warp, f32x2).
// ---------------------------------------------------------------------------
__global__ __launch_bounds__(256, 2)
void k_agg_gemm(const float* __restrict__ adj, const float* __restrict__ w0,
                const float* __restrict__ bias, float* __restrict__ out)
{
    __shared__ float2 sW[FDIM * 32];
    __shared__ float  sx[8][8][FDIM];

    const int tid = threadIdx.x;
    const float2* w02 = (const float2*)w0;
    for (int i = tid; i < FDIM * 32; i += blockDim.x) sW[i] = w02[i];
    __syncthreads();

    const int lane = tid & 31, wsub = tid >> 5;
    const int hl = lane >> 4, fl = lane & 15;
    const int gw = blockIdx.x * 8 + wsub;
    const int nwarps = gridDim.x * 8;

    const float4* Xn4 = (const float4*)g_xn;
    const float2  bi  = ((const float2*)bias)[lane];
    unsigned long long biP;
    memcpy(&biP, &bi, 8);

    for (int c = gw; c < NN / 8; c += nwarps) {
        const int base = c * 8;

        // Phase A: aggregate 8 nodes (2 per pass, half-warp each) into shared
        #pragma unroll
        for (int p = 0; p < 4; p++) {
            const int n = base + 2 * p + hl;
            float aj[DEG];
            int js[DEG];
            {
                const float4* a4 = (const float4*)(adj + (size_t)n * DEG);
                const int4* nb4 = (const int4*)(g_nbr + n * DEG);
                #pragma unroll
                for (int q = 0; q < 4; q++) {
                    *(float4*)&aj[q * 4] = a4[q];
                    *(int4*)&js[q * 4]   = nb4[q];
                }
            }
            float4 acc = make_float4(0.f, 0.f, 0.f, 0.f);
            #pragma unroll
            for (int d = 0; d < DEG; d++) {
                const float4 s = Xn4[js[d] * 16 + fl];
                acc.x += aj[d] * s.x;  acc.y += aj[d] * s.y;
                acc.z += aj[d] * s.z;  acc.w += aj[d] * s.w;
            }
            *(float4*)&sx[wsub][2 * p + hl][fl * 4] = acc;
        }
        __syncwarp();

        // Phase B: out rows = sx @ W0 + bias
        unsigned long long o[8];
        #pragma unroll
        for (int r = 0; r < 8; r++) o[r] = biP;

        #pragma unroll 8
        for (int k = 0; k < FDIM; k++) {
            unsigned long long wv;
            memcpy(&wv, &sW[k * 32 + lane], 8);
            #pragma unroll
            for (int r = 0; r < 8; r++)
                fma2(o[r], pack2(sx[wsub][r][k]), wv);
        }
        #pragma unroll
        for (int r = 0; r < 8; r++)
            ((float2*)out)[(base + r) * 32 + lane] = unpack2(o[r]);
        __syncwarp();
    }
}

// ---------------------------------------------------------------------------
extern "C" void kernel_launch(void* const* d_in, const int* in_sizes, int n_in,
                              void* d_out, int out_size)
{
    const float* x    = (const float*)d_in[0];
    const float* w0   = (const float*)d_in[1];
    const float* wm   = (const float*)d_in[2];
    const float* bias = (const float*)d_in[3];
    const float* adj  = (const float*)d_in[4];
    const float* drop = (const float*)d_in[5];
    const int*   nbrr = (const int*)d_in[6];
    float* out = (float*)d_out;

    k_detect  <<<64, 256>>>(nbrr);
    k_convert <<<148, 256>>>(nbrr);
    k_gemm_tb <<<296, 256>>>(x, wm);
    k_edge    <<<888, 256>>>(x, drop);
    k_agg_gemm<<<296, 256>>>(adj, w0, bias, out);
}

// round 10
// speedup vs baseline: 1.0172x; 1.0172x over previous
#include <cuda_runtime.h>
#include <cstdint>
#include <cstring>

#define NN   50000
#define DEG  16
#define FDIM 64
#define NE   (NN * DEG)

// Scratch (allocation-free rule)
__device__ __align__(16) float g_T[NN * FDIM];
__device__ __align__(16) float g_BX[NN * FDIM * 2];  // per node: [B row (64f)][x row (64f)]
__device__ __align__(16) float g_xn[NN * FDIM];      // x_new
__device__ __align__(16) int   g_nbr[NE];
__device__ int g_is32 = 0;

// ---- packed f32x2 helpers (Blackwell) -------------------------------------
__device__ __forceinline__ unsigned long long pack2(float v) {
    unsigned long long r;
    asm("mov.b64 %0, {%1, %1};" : "=l"(r) : "f"(v));
    return r;
}
__device__ __forceinline__ void fma2(unsigned long long& d,
                                     unsigned long long a, unsigned long long b) {
    asm("fma.rn.f32x2 %0, %1, %2, %0;" : "+l"(d) : "l"(a), "l"(b));
}
__device__ __forceinline__ float2 unpack2(unsigned long long v) {
    float2 f;
    asm("mov.b64 {%0, %1}, %2;" : "=f"(f.x), "=f"(f.y) : "l"(v));
    return f;
}
__device__ __forceinline__ float sigmoid_fast(float z) {
    float t;
    asm("tanh.approx.f32 %0, %1;" : "=f"(t) : "f"(0.5f * z));
    return fmaf(0.5f, t, 0.5f);
}

// ---------------------------------------------------------------------------
// K0: dtype sniff + convert (int64 lo-words vs int32)
// ---------------------------------------------------------------------------
__global__ void k_detect(const int* __restrict__ raw)
{
    int i = (blockIdx.x * blockDim.x + threadIdx.x) * 2 + 1;
    const int lim = NE < (1 << 18) ? NE : (1 << 18);
    for (; i < lim; i += gridDim.x * blockDim.x * 2)
        if (raw[i] != 0) { atomicExch(&g_is32, 1); return; }
}
__global__ void k_convert(const int* __restrict__ raw)
{
    const int is32 = g_is32;
    for (int i = blockIdx.x * blockDim.x + threadIdx.x; i < NE;
         i += gridDim.x * blockDim.x)
        g_nbr[i] = is32 ? raw[i] : raw[2 * i];
}

// ---------------------------------------------------------------------------
// K1: T = x@wm_top; g_BX[n] = {x@wm_bot row, x row} interleaved (512B/node).
// 8 rows/warp amortized weights, f32x2 FMA.
// ---------------------------------------------------------------------------
__global__ __launch_bounds__(256, 2)
void k_gemm_tb(const float* __restrict__ x, const float* __restrict__ wm)
{
    __shared__ float2 sT[FDIM * 32];
    __shared__ float2 sB[FDIM * 32];
    __shared__ float  sx[8][8][FDIM];     // [warp][row][k]

    const int tid = threadIdx.x;
    const float2* wm2 = (const float2*)wm;
    for (int i = tid; i < FDIM * 32; i += blockDim.x) {
        sT[i] = wm2[i];
        sB[i] = wm2[FDIM * 32 + i];
    }
    __syncthreads();

    const int lane = tid & 31, wsub = tid >> 5;
    const int gw = blockIdx.x * 8 + wsub;
    const int nwarps = gridDim.x * 8;
    const float2* x2 = (const float2*)x;

    for (int c = gw; c < NN / 8; c += nwarps) {
        const int base = c * 8;
        #pragma unroll
        for (int r = 0; r < 8; r++)
            ((float2*)sx[wsub][r])[lane] = x2[(base + r) * 32 + lane];
        __syncwarp();

        unsigned long long tA[8], bA[8];
        #pragma unroll
        for (int r = 0; r < 8; r++) { tA[r] = 0ull; bA[r] = 0ull; }

        #pragma unroll 8
        for (int k = 0; k < FDIM; k++) {
            unsigned long long wt, wb;
            memcpy(&wt, &sT[k * 32 + lane], 8);
            memcpy(&wb, &sB[k * 32 + lane], 8);
            #pragma unroll
            for (int r = 0; r < 8; r++) {
                const unsigned long long xk = pack2(sx[wsub][r][k]);
                fma2(tA[r], xk, wt);
                fma2(bA[r], xk, wb);
            }
        }
        #pragma unroll
        for (int r = 0; r < 8; r++) {
            ((float2*)g_T)[(base + r) * 32 + lane] = unpack2(tA[r]);
            // interleaved record: B row then x row
            ((float2*)g_BX)[(base + r) * 64 + lane]      = unpack2(bA[r]);
            ((float2*)g_BX)[(base + r) * 64 + 32 + lane] =
                ((float2*)sx[wsub][r])[lane];
        }
        __syncwarp();
    }
}

// ---------------------------------------------------------------------------
// K2: x_new[n] = x[n] + sum_d sigmoid(T[n]+B[j])*drop[n,d]*x[j]
// Half-warp per node, float4 lanes. 2 CTAs/SM, 128-reg budget: registers buy
// gather MLP (R7 showed 3 CTAs/80 regs is a net loss).
// B and x for neighbor j come from one contiguous 512B g_BX record.
// ---------------------------------------------------------------------------
__global__ __launch_bounds__(256, 2)
void k_edge(const float* __restrict__ x, const float* __restrict__ drop)
{
    const int tid  = threadIdx.x;
    const int lane = tid & 31;
    const int hl   = lane >> 4;          // which node of the pair
    const int fl   = lane & 15;          // float4 slot
    const int gw   = blockIdx.x * 8 + (tid >> 5);
    const int nwarps = gridDim.x * 8;

    const float4* x4  = (const float4*)x;
    const float4* BX4 = (const float4*)g_BX;
    const float4* T4  = (const float4*)g_T;

    for (int c = gw; c < NN / 2; c += nwarps) {
        const int n = c * 2 + hl;
        const float4 t = T4[n * 16 + fl];
        float4 a = x4[n * 16 + fl];

        int js[DEG];
        {
            const int4* nb4 = (const int4*)(g_nbr + n * DEG);
            #pragma unroll
            for (int q = 0; q < 4; q++) *(int4*)&js[q * 4] = nb4[q];
        }
        const float4* dm = (const float4*)(drop + (size_t)n * DEG * FDIM);

        #pragma unroll
        for (int d = 0; d < DEG; d++) {
            const int j = js[d];
            const float4 b  = BX4[j * 32 + fl];        // B half of record
            const float4 xj = BX4[j * 32 + 16 + fl];   // x half of record
            const float4 m  = __ldcs(dm + d * 16 + fl);
            a.x += sigmoid_fast(t.x + b.x) * m.x * xj.x;
            a.y += sigmoid_fast(t.y + b.y) * m.y * xj.y;
            a.z += sigmoid_fast(t.z + b.z) * m.z * xj.z;
            a.w += sigmoid_fast(t.w + b.w) * m.w * xj.w;
        }
        ((float4*)g_xn)[n * 16 + fl] = a;
    }
}

// ---------------------------------------------------------------------------
// K34 (fused): agg[n] = sum_d adj[n,d]*x_new[nbr[n,d]] staged into shared,
// then out = agg @ weight_0 + bias   (8 rows/warp, f32x2).
// ---------------------------------------------------------------------------
__global__ __launch_bounds__(256, 2)
void k_agg_gemm(const float* __restrict__ adj, const float* __restrict__ w0,
                const float* __restrict__ bias, float* __restrict__ out)
{
    __shared__ float2 sW[FDIM * 32];
    __shared__ float  sx[8][8][FDIM];

    const int tid = threadIdx.x;
    const float2* w02 = (const float2*)w0;
    for (int i = tid; i < FDIM * 32; i += blockDim.x) sW[i] = w02[i];
    __syncthreads();

    const int lane = tid & 31, wsub = tid >> 5;
    const int hl = lane >> 4, fl = lane & 15;
    const int gw = blockIdx.x * 8 + wsub;
    const int nwarps = gridDim.x * 8;

    const float4* Xn4 = (const float4*)g_xn;
    const float2  bi  = ((const float2*)bias)[lane];
    unsigned long long biP;
    memcpy(&biP, &bi, 8);

    for (int c = gw; c < NN / 8; c += nwarps) {
        const int base = c * 8;

        // Phase A: aggregate 8 nodes (2 per pass, half-warp each) into shared
        #pragma unroll
        for (int p = 0; p < 4; p++) {
            const int n = base + 2 * p + hl;
            float aj[DEG];
            int js[DEG];
            {
                const float4* a4 = (const float4*)(adj + (size_t)n * DEG);
                const int4* nb4 = (const int4*)(g_nbr + n * DEG);
                #pragma unroll
                for (int q = 0; q < 4; q++) {
                    *(float4*)&aj[q * 4] = __ldcs(a4 + q);
                    *(int4*)&js[q * 4]   = nb4[q];
                }
            }
            float4 acc = make_float4(0.f, 0.f, 0.f, 0.f);
            #pragma unroll
            for (int d = 0; d < DEG; d++) {
                const float4 s = Xn4[js[d] * 16 + fl];
                acc.x += aj[d] * s.x;  acc.y += aj[d] * s.y;
                acc.z += aj[d] * s.z;  acc.w += aj[d] * s.w;
            }
            *(float4*)&sx[wsub][2 * p + hl][fl * 4] = acc;
        }
        __syncwarp();

        // Phase B: out rows = sx @ W0 + bias
        unsigned long long o[8];
        #pragma unroll
        for (int r = 0; r < 8; r++) o[r] = biP;

        #pragma unroll 8
        for (int k = 0; k < FDIM; k++) {
            unsigned long long wv;
            memcpy(&wv, &sW[k * 32 + lane], 8);
            #pragma unroll
            for (int r = 0; r < 8; r++)
                fma2(o[r], pack2(sx[wsub][r][k]), wv);
        }
        #pragma unroll
        for (int r = 0; r < 8; r++)
            ((float2*)out)[(base + r) * 32 + lane] = unpack2(o[r]);
        __syncwarp();
    }
}

// ---------------------------------------------------------------------------
extern "C" void kernel_launch(void* const* d_in, const int* in_sizes, int n_in,
                              void* d_out, int out_size)
{
    const float* x    = (const float*)d_in[0];
    const float* w0   = (const float*)d_in[1];
    const float* wm   = (const float*)d_in[2];
    const float* bias = (const float*)d_in[3];
    const float* adj  = (const float*)d_in[4];
    const float* drop = (const float*)d_in[5];
    const int*   nbrr = (const int*)d_in[6];
    float* out = (float*)d_out;

    k_detect  <<<64, 256>>>(nbrr);
    k_convert <<<148, 256>>>(nbrr);
    k_gemm_tb <<<296, 256>>>(x, wm);
    k_edge    <<<592, 256>>>(x, drop);
    k_agg_gemm<<<296, 256>>>(adj, w0, bias, out);
}

// round 11
// speedup vs baseline: 1.0506x; 1.0328x over previous
#include <cuda_runtime.h>
#include <cstdint>
#include <cstring>

#define NN   50000
#define DEG  16
#define FDIM 64
#define NE   (NN * DEG)

// Scratch (allocation-free rule)
__device__ __align__(16) float g_T[NN * FDIM];
__device__ __align__(16) float g_B[NN * FDIM];
__device__ __align__(16) float g_xn[NN * FDIM];   // x_new
__device__ __align__(16) int   g_nbr[NE];
__device__ int g_is32 = 0;

// ---- packed f32x2 helpers (Blackwell) -------------------------------------
__device__ __forceinline__ unsigned long long pack2(float v) {
    unsigned long long r;
    asm("mov.b64 %0, {%1, %1};" : "=l"(r) : "f"(v));
    return r;
}
__device__ __forceinline__ void fma2(unsigned long long& d,
                                     unsigned long long a, unsigned long long b) {
    asm("fma.rn.f32x2 %0, %1, %2, %0;" : "+l"(d) : "l"(a), "l"(b));
}
__device__ __forceinline__ float2 unpack2(unsigned long long v) {
    float2 f;
    asm("mov.b64 {%0, %1}, %2;" : "=f"(f.x), "=f"(f.y) : "l"(v));
    return f;
}
__device__ __forceinline__ float sigmoid_fast(float z) {
    float t;
    asm("tanh.approx.f32 %0, %1;" : "=f"(t) : "f"(0.5f * z));
    return fmaf(0.5f, t, 0.5f);
}

// ---------------------------------------------------------------------------
// K0: dtype sniff + convert (int64 lo-words vs int32)
// ---------------------------------------------------------------------------
__global__ void k_detect(const int* __restrict__ raw)
{
    int i = (blockIdx.x * blockDim.x + threadIdx.x) * 2 + 1;
    const int lim = NE < (1 << 18) ? NE : (1 << 18);
    for (; i < lim; i += gridDim.x * blockDim.x * 2)
        if (raw[i] != 0) { atomicExch(&g_is32, 1); return; }
}
__global__ void k_convert(const int* __restrict__ raw)
{
    const int is32 = g_is32;
    for (int i = blockIdx.x * blockDim.x + threadIdx.x; i < NE;
         i += gridDim.x * blockDim.x)
        g_nbr[i] = is32 ? raw[i] : raw[2 * i];
}

// ---------------------------------------------------------------------------
// K1: T = x@wm_top, B = x@wm_bot.  8 rows/warp amortized weights, f32x2 FMA.
// (R6 version — split g_T/g_B; g_BX interleave measured as a regression.)
// ---------------------------------------------------------------------------
__global__ __launch_bounds__(256, 2)
void k_gemm_tb(const float* __restrict__ x, const float* __restrict__ wm)
{
    __shared__ float2 sT[FDIM * 32];
    __shared__ float2 sB[FDIM * 32];
    __shared__ float  sx[8][8][FDIM];     // [warp][row][k]

    const int tid = threadIdx.x;
    const float2* wm2 = (const float2*)wm;
    for (int i = tid; i < FDIM * 32; i += blockDim.x) {
        sT[i] = wm2[i];
        sB[i] = wm2[FDIM * 32 + i];
    }
    __syncthreads();

    const int lane = tid & 31, wsub = tid >> 5;
    const int gw = blockIdx.x * 8 + wsub;
    const int nwarps = gridDim.x * 8;
    const float2* x2 = (const float2*)x;

    for (int c = gw; c < NN / 8; c += nwarps) {
        const int base = c * 8;
        #pragma unroll
        for (int r = 0; r < 8; r++)
            ((float2*)sx[wsub][r])[lane] = x2[(base + r) * 32 + lane];
        __syncwarp();

        unsigned long long tA[8], bA[8];
        #pragma unroll
        for (int r = 0; r < 8; r++) { tA[r] = 0ull; bA[r] = 0ull; }

        #pragma unroll 8
        for (int k = 0; k < FDIM; k++) {
            unsigned long long wt, wb;
            memcpy(&wt, &sT[k * 32 + lane], 8);
            memcpy(&wb, &sB[k * 32 + lane], 8);
            #pragma unroll
            for (int r = 0; r < 8; r++) {
                const unsigned long long xk = pack2(sx[wsub][r][k]);
                fma2(tA[r], xk, wt);
                fma2(bA[r], xk, wb);
            }
        }
        #pragma unroll
        for (int r = 0; r < 8; r++) {
            ((float2*)g_T)[(base + r) * 32 + lane] = unpack2(tA[r]);
            ((float2*)g_B)[(base + r) * 32 + lane] = unpack2(bA[r]);
        }
        __syncwarp();
    }
}

// ---------------------------------------------------------------------------
// K2: x_new[n] = x[n] + sum_d sigmoid(T[n]+B[j])*drop[n,d]*x[j]
// Half-warp per node pair: 2 nodes interleaved per half-warp (4 nodes/warp)
// to double per-warp gather MLP at unchanged occupancy (2 CTAs, 128 regs).
// ---------------------------------------------------------------------------
__global__ __launch_bounds__(256, 2)
void k_edge(const float* __restrict__ x, const float* __restrict__ drop)
{
    const int tid  = threadIdx.x;
    const int lane = tid & 31;
    const int hl   = lane >> 4;          // half-warp id
    const int fl   = lane & 15;          // float4 slot
    const int gw   = blockIdx.x * 8 + (tid >> 5);
    const int nwarps = gridDim.x * 8;

    const float4* x4 = (const float4*)x;
    const float4* B4 = (const float4*)g_B;
    const float4* T4 = (const float4*)g_T;

    for (int c = gw; c < NN / 4; c += nwarps) {
        const int n0 = c * 4 + hl * 2;   // this half-warp's two nodes
        const int n1 = n0 + 1;

        const float4 t0 = T4[n0 * 16 + fl];
        const float4 t1 = T4[n1 * 16 + fl];
        float4 a0 = x4[n0 * 16 + fl];
        float4 a1 = x4[n1 * 16 + fl];

        int js0[DEG], js1[DEG];
        {
            const int4* nb0 = (const int4*)(g_nbr + n0 * DEG);
            const int4* nb1 = (const int4*)(g_nbr + n1 * DEG);
            #pragma unroll
            for (int q = 0; q < 4; q++) {
                *(int4*)&js0[q * 4] = nb0[q];
                *(int4*)&js1[q * 4] = nb1[q];
            }
        }
        const float4* dm0 = (const float4*)(drop + (size_t)n0 * DEG * FDIM);
        const float4* dm1 = (const float4*)(drop + (size_t)n1 * DEG * FDIM);

        #pragma unroll
        for (int d = 0; d < DEG; d++) {
            const int j0 = js0[d], j1 = js1[d];
            const float4 b0  = B4[j0 * 16 + fl];
            const float4 b1  = B4[j1 * 16 + fl];
            const float4 xj0 = x4[j0 * 16 + fl];
            const float4 xj1 = x4[j1 * 16 + fl];
            const float4 m0  = __ldcs(dm0 + d * 16 + fl);
            const float4 m1  = __ldcs(dm1 + d * 16 + fl);
            a0.x += sigmoid_fast(t0.x + b0.x) * m0.x * xj0.x;
            a0.y += sigmoid_fast(t0.y + b0.y) * m0.y * xj0.y;
            a0.z += sigmoid_fast(t0.z + b0.z) * m0.z * xj0.z;
            a0.w += sigmoid_fast(t0.w + b0.w) * m0.w * xj0.w;
            a1.x += sigmoid_fast(t1.x + b1.x) * m1.x * xj1.x;
            a1.y += sigmoid_fast(t1.y + b1.y) * m1.y * xj1.y;
            a1.z += sigmoid_fast(t1.z + b1.z) * m1.z * xj1.z;
            a1.w += sigmoid_fast(t1.w + b1.w) * m1.w * xj1.w;
        }
        ((float4*)g_xn)[n0 * 16 + fl] = a0;
        ((float4*)g_xn)[n1 * 16 + fl] = a1;
    }
}

// ---------------------------------------------------------------------------
// K34 (fused): agg[n] = sum_d adj[n,d]*x_new[nbr[n,d]] staged into shared,
// then out = agg @ weight_0 + bias   (8 rows/warp, f32x2).
// ---------------------------------------------------------------------------
__global__ __launch_bounds__(256, 2)
void k_agg_gemm(const float* __restrict__ adj, const float* __restrict__ w0,
                const float* __restrict__ bias, float* __restrict__ out)
{
    __shared__ float2 sW[FDIM * 32];
    __shared__ float  sx[8][8][FDIM];

    const int tid = threadIdx.x;
    const float2* w02 = (const float2*)w0;
    for (int i = tid; i < FDIM * 32; i += blockDim.x) sW[i] = w02[i];
    __syncthreads();

    const int lane = tid & 31, wsub = tid >> 5;
    const int hl = lane >> 4, fl = lane & 15;
    const int gw = blockIdx.x * 8 + wsub;
    const int nwarps = gridDim.x * 8;

    const float4* Xn4 = (const float4*)g_xn;
    const float2  bi  = ((const float2*)bias)[lane];
    unsigned long long biP;
    memcpy(&biP, &bi, 8);

    for (int c = gw; c < NN / 8; c += nwarps) {
        const int base = c * 8;

        // Phase A: aggregate 8 nodes (2 per pass, half-warp each) into shared
        #pragma unroll
        for (int p = 0; p < 4; p++) {
            const int n = base + 2 * p + hl;
            float aj[DEG];
            int js[DEG];
            {
                const float4* a4 = (const float4*)(adj + (size_t)n * DEG);
                const int4* nb4 = (const int4*)(g_nbr + n * DEG);
                #pragma unroll
                for (int q = 0; q < 4; q++) {
                    *(float4*)&aj[q * 4] = __ldcs(a4 + q);
                    *(int4*)&js[q * 4]   = nb4[q];
                }
            }
            float4 acc = make_float4(0.f, 0.f, 0.f, 0.f);
            #pragma unroll
            for (int d = 0; d < DEG; d++) {
                const float4 s = Xn4[js[d] * 16 + fl];
                acc.x += aj[d] * s.x;  acc.y += aj[d] * s.y;
                acc.z += aj[d] * s.z;  acc.w += aj[d] * s.w;
            }
            *(float4*)&sx[wsub][2 * p + hl][fl * 4] = acc;
        }
        __syncwarp();

        // Phase B: out rows = sx @ W0 + bias
        unsigned long long o[8];
        #pragma unroll
        for (int r = 0; r < 8; r++) o[r] = biP;

        #pragma unroll 8
        for (int k = 0; k < FDIM; k++) {
            unsigned long long wv;
            memcpy(&wv, &sW[k * 32 + lane], 8);
            #pragma unroll
            for (int r = 0; r < 8; r++)
                fma2(o[r], pack2(sx[wsub][r][k]), wv);
        }
        #pragma unroll
        for (int r = 0; r < 8; r++)
            ((float2*)out)[(base + r) * 32 + lane] = unpack2(o[r]);
        __syncwarp();
    }
}

// ---------------------------------------------------------------------------
extern "C" void kernel_launch(void* const* d_in, const int* in_sizes, int n_in,
                              void* d_out, int out_size)
{
    const float* x    = (const float*)d_in[0];
    const float* w0   = (const float*)d_in[1];
    const float* wm   = (const float*)d_in[2];
    const float* bias = (const float*)d_in[3];
    const float* adj  = (const float*)d_in[4];
    const float* drop = (const float*)d_in[5];
    const int*   nbrr = (const int*)d_in[6];
    float* out = (float*)d_out;

    k_detect  <<<64, 256>>>(nbrr);
    k_convert <<<148, 256>>>(nbrr);
    k_gemm_tb <<<296, 256>>>(x, wm);
    k_edge    <<<592, 256>>>(x, drop);
    k_agg_gemm<<<296, 256>>>(adj, w0, bias, out);
}

// round 12
// speedup vs baseline: 1.0714x; 1.0198x over previous
#include <cuda_runtime.h>
#include <cstdint>
#include <cstring>

#define NN   50000
#define DEG  16
#define FDIM 64
#define NE   (NN * DEG)

// Scratch (allocation-free rule)
__device__ __align__(16) float g_T[NN * FDIM];
__device__ __align__(16) float g_B[NN * FDIM];
__device__ __align__(16) float g_xn[NN * FDIM];   // x_new
__device__ __align__(16) int   g_nbr[NE];
__device__ int g_is32 = 0;

// ---- packed f32x2 helpers (Blackwell) -------------------------------------
__device__ __forceinline__ unsigned long long pack2(float v) {
    unsigned long long r;
    asm("mov.b64 %0, {%1, %1};" : "=l"(r) : "f"(v));
    return r;
}
__device__ __forceinline__ void fma2(unsigned long long& d,
                                     unsigned long long a, unsigned long long b) {
    asm("fma.rn.f32x2 %0, %1, %2, %0;" : "+l"(d) : "l"(a), "l"(b));
}
__device__ __forceinline__ float2 unpack2(unsigned long long v) {
    float2 f;
    asm("mov.b64 {%0, %1}, %2;" : "=f"(f.x), "=f"(f.y) : "l"(v));
    return f;
}
__device__ __forceinline__ float sigmoid_fast(float z) {
    float t;
    asm("tanh.approx.f32 %0, %1;" : "=f"(t) : "f"(0.5f * z));
    return fmaf(0.5f, t, 0.5f);
}

// ---------------------------------------------------------------------------
// K0: dtype sniff + convert (int64 lo-words vs int32)
// ---------------------------------------------------------------------------
__global__ void k_detect(const int* __restrict__ raw)
{
    int i = (blockIdx.x * blockDim.x + threadIdx.x) * 2 + 1;
    const int lim = NE < (1 << 18) ? NE : (1 << 18);
    for (; i < lim; i += gridDim.x * blockDim.x * 2)
        if (raw[i] != 0) { atomicExch(&g_is32, 1); return; }
}
__global__ void k_convert(const int* __restrict__ raw)
{
    const int is32 = g_is32;
    for (int i = blockIdx.x * blockDim.x + threadIdx.x; i < NE;
         i += gridDim.x * blockDim.x)
        g_nbr[i] = is32 ? raw[i] : raw[2 * i];
}

// ---------------------------------------------------------------------------
// K1: T = x@wm_top, B = x@wm_bot.  8 rows/warp amortized weights, f32x2 FMA.
// ---------------------------------------------------------------------------
__global__ __launch_bounds__(256, 2)
void k_gemm_tb(const float* __restrict__ x, const float* __restrict__ wm)
{
    __shared__ float2 sT[FDIM * 32];
    __shared__ float2 sB[FDIM * 32];
    __shared__ float  sx[8][8][FDIM];     // [warp][row][k]

    const int tid = threadIdx.x;
    const float2* wm2 = (const float2*)wm;
    for (int i = tid; i < FDIM * 32; i += blockDim.x) {
        sT[i] = wm2[i];
        sB[i] = wm2[FDIM * 32 + i];
    }
    __syncthreads();

    const int lane = tid & 31, wsub = tid >> 5;
    const int gw = blockIdx.x * 8 + wsub;
    const int nwarps = gridDim.x * 8;
    const float2* x2 = (const float2*)x;

    for (int c = gw; c < NN / 8; c += nwarps) {
        const int base = c * 8;
        #pragma unroll
        for (int r = 0; r < 8; r++)
            ((float2*)sx[wsub][r])[lane] = x2[(base + r) * 32 + lane];
        __syncwarp();

        unsigned long long tA[8], bA[8];
        #pragma unroll
        for (int r = 0; r < 8; r++) { tA[r] = 0ull; bA[r] = 0ull; }

        #pragma unroll 8
        for (int k = 0; k < FDIM; k++) {
            unsigned long long wt, wb;
            memcpy(&wt, &sT[k * 32 + lane], 8);
            memcpy(&wb, &sB[k * 32 + lane], 8);
            #pragma unroll
            for (int r = 0; r < 8; r++) {
                const unsigned long long xk = pack2(sx[wsub][r][k]);
                fma2(tA[r], xk, wt);
                fma2(bA[r], xk, wb);
            }
        }
        #pragma unroll
        for (int r = 0; r < 8; r++) {
            ((float2*)g_T)[(base + r) * 32 + lane] = unpack2(tA[r]);
            ((float2*)g_B)[(base + r) * 32 + lane] = unpack2(bA[r]);
        }
        __syncwarp();
    }
}

// ---------------------------------------------------------------------------
// K2: x_new[n] = x[n] + sum_d sigmoid(T[n]+B[j])*drop[n,d]*x[j]
// R6 structure (half-warp per node, float4 lanes, 2 CTAs/128 regs) plus
// EXPLICIT drop_mask prefetch in two 8-deep register batches: guarantees
// MLP=8 on the DRAM-latency-bound drop stream regardless of ptxas scheduling.
// ---------------------------------------------------------------------------
__global__ __launch_bounds__(256, 2)
void k_edge(const float* __restrict__ x, const float* __restrict__ drop)
{
    const int tid  = threadIdx.x;
    const int lane = tid & 31;
    const int hl   = lane >> 4;          // which node of the pair
    const int fl   = lane & 15;          // float4 slot
    const int gw   = blockIdx.x * 8 + (tid >> 5);
    const int nwarps = gridDim.x * 8;

    const float4* x4 = (const float4*)x;
    const float4* B4 = (const float4*)g_B;
    const float4* T4 = (const float4*)g_T;

    for (int c = gw; c < NN / 2; c += nwarps) {
        const int n = c * 2 + hl;
        const float4 t = T4[n * 16 + fl];
        float4 a = x4[n * 16 + fl];

        int js[DEG];
        {
            const int4* nb4 = (const int4*)(g_nbr + n * DEG);
            #pragma unroll
            for (int q = 0; q < 4; q++) *(int4*)&js[q * 4] = nb4[q];
        }
        const float4* dm = (const float4*)(drop + (size_t)n * DEG * FDIM);

        float4 mbuf[8];
        #pragma unroll
        for (int half = 0; half < 2; half++) {
            const int d0 = half * 8;
            // front-batch 8 streaming drop loads (DRAM MLP = 8)
            #pragma unroll
            for (int q = 0; q < 8; q++)
                mbuf[q] = __ldcs(dm + (d0 + q) * 16 + fl);
            #pragma unroll
            for (int q = 0; q < 8; q++) {
                const int j = js[d0 + q];
                const float4 b  = B4[j * 16 + fl];
                const float4 xj = x4[j * 16 + fl];
                const float4 m  = mbuf[q];
                a.x += sigmoid_fast(t.x + b.x) * m.x * xj.x;
                a.y += sigmoid_fast(t.y + b.y) * m.y * xj.y;
                a.z += sigmoid_fast(t.z + b.z) * m.z * xj.z;
                a.w += sigmoid_fast(t.w + b.w) * m.w * xj.w;
            }
        }
        ((float4*)g_xn)[n * 16 + fl] = a;
    }
}

// ---------------------------------------------------------------------------
// K34 (fused): agg[n] = sum_d adj[n,d]*x_new[nbr[n,d]] staged into shared,
// then out = agg @ weight_0 + bias   (8 rows/warp, f32x2).
// 3 CTAs/SM: phase-A has a single L2-resident gather stream with indices
// prefetched, so the 85-reg cap shouldn't strangle MLP; extra warps cover
// L2 latency.
// ---------------------------------------------------------------------------
__global__ __launch_bounds__(256, 3)
void k_agg_gemm(const float* __restrict__ adj, const float* __restrict__ w0,
                const float* __restrict__ bias, float* __restrict__ out)
{
    __shared__ float2 sW[FDIM * 32];
    __shared__ float  sx[8][8][FDIM];

    const int tid = threadIdx.x;
    const float2* w02 = (const float2*)w0;
    for (int i = tid; i < FDIM * 32; i += blockDim.x) sW[i] = w02[i];
    __syncthreads();

    const int lane = tid & 31, wsub = tid >> 5;
    const int hl = lane >> 4, fl = lane & 15;
    const int gw = blockIdx.x * 8 + wsub;
    const int nwarps = gridDim.x * 8;

    const float4* Xn4 = (const float4*)g_xn;
    const float2  bi  = ((const float2*)bias)[lane];
    unsigned long long biP;
    memcpy(&biP, &bi, 8);

    for (int c = gw; c < NN / 8; c += nwarps) {
        const int base = c * 8;

        // Phase A: aggregate 8 nodes (2 per pass, half-warp each) into shared
        #pragma unroll
        for (int p = 0; p < 4; p++) {
            const int n = base + 2 * p + hl;
            float aj[DEG];
            int js[DEG];
            {
                const float4* a4 = (const float4*)(adj + (size_t)n * DEG);
                const int4* nb4 = (const int4*)(g_nbr + n * DEG);
                #pragma unroll
                for (int q = 0; q < 4; q++) {
                    *(float4*)&aj[q * 4] = __ldcs(a4 + q);
                    *(int4*)&js[q * 4]   = nb4[q];
                }
            }
            float4 acc = make_float4(0.f, 0.f, 0.f, 0.f);
            #pragma unroll
            for (int d = 0; d < DEG; d++) {
                const float4 s = Xn4[js[d] * 16 + fl];
                acc.x += aj[d] * s.x;  acc.y += aj[d] * s.y;
                acc.z += aj[d] * s.z;  acc.w += aj[d] * s.w;
            }
            *(float4*)&sx[wsub][2 * p + hl][fl * 4] = acc;
        }
        __syncwarp();

        // Phase B: out rows = sx @ W0 + bias
        unsigned long long o[8];
        #pragma unroll
        for (int r = 0; r < 8; r++) o[r] = biP;

        #pragma unroll 8
        for (int k = 0; k < FDIM; k++) {
            unsigned long long wv;
            memcpy(&wv, &sW[k * 32 + lane], 8);
            #pragma unroll
            for (int r = 0; r < 8; r++)
                fma2(o[r], pack2(sx[wsub][r][k]), wv);
        }
        #pragma unroll
        for (int r = 0; r < 8; r++)
            ((float2*)out)[(base + r) * 32 + lane] = unpack2(o[r]);
        __syncwarp();
    }
}

// ---------------------------------------------------------------------------
extern "C" void kernel_launch(void* const* d_in, const int* in_sizes, int n_in,
                              void* d_out, int out_size)
{
    const float* x    = (const float*)d_in[0];
    const float* w0   = (const float*)d_in[1];
    const float* wm   = (const float*)d_in[2];
    const float* bias = (const float*)d_in[3];
    const float* adj  = (const float*)d_in[4];
    const float* drop = (const float*)d_in[5];
    const int*   nbrr = (const int*)d_in[6];
    float* out = (float*)d_out;

    k_detect  <<<64, 256>>>(nbrr);
    k_convert <<<148, 256>>>(nbrr);
    k_gemm_tb <<<296, 256>>>(x, wm);
    k_edge    <<<592, 256>>>(x, drop);
    k_agg_gemm<<<444, 256>>>(adj, w0, bias, out);
}

// round 13
// speedup vs baseline: 1.1818x; 1.1030x over previous
#include <cuda_runtime.h>
#include <cuda_fp16.h>
#include <cstdint>
#include <cstring>

#define NN   50000
#define DEG  16
#define FDIM 64
#define NE   (NN * DEG)

// Scratch (allocation-free rule)
__device__ __align__(16) float g_T[NN * FDIM];
__device__ __align__(16) uint4 g_bxh[NN * 16];   // per node: 16B chunks {B[4f..],x[4f..]} fp16
__device__ __align__(16) uint2 g_xnh[NN * 16];   // x_new fp16, 8B per 4-feature chunk
__device__ __align__(16) int   g_nbr[NE];
__device__ int g_is32 = 0;

// ---- packed f32x2 helpers (Blackwell) -------------------------------------
__device__ __forceinline__ unsigned long long pack2(float v) {
    unsigned long long r;
    asm("mov.b64 %0, {%1, %1};" : "=l"(r) : "f"(v));
    return r;
}
__device__ __forceinline__ void fma2(unsigned long long& d,
                                     unsigned long long a, unsigned long long b) {
    asm("fma.rn.f32x2 %0, %1, %2, %0;" : "+l"(d) : "l"(a), "l"(b));
}
__device__ __forceinline__ float2 unpack2(unsigned long long v) {
    float2 f;
    asm("mov.b64 {%0, %1}, %2;" : "=f"(f.x), "=f"(f.y) : "l"(v));
    return f;
}
__device__ __forceinline__ float sigmoid_fast(float z) {
    float t;
    asm("tanh.approx.f32 %0, %1;" : "=f"(t) : "f"(0.5f * z));
    return fmaf(0.5f, t, 0.5f);
}

// ---------------------------------------------------------------------------
// K0: dtype sniff + convert (int64 lo-words vs int32)
// ---------------------------------------------------------------------------
__global__ void k_detect(const int* __restrict__ raw)
{
    int i = (blockIdx.x * blockDim.x + threadIdx.x) * 2 + 1;
    const int lim = NE < (1 << 18) ? NE : (1 << 18);
    for (; i < lim; i += gridDim.x * blockDim.x * 2)
        if (raw[i] != 0) { atomicExch(&g_is32, 1); return; }
}
__global__ void k_convert(const int* __restrict__ raw)
{
    const int is32 = g_is32;
    for (int i = blockIdx.x * blockDim.x + threadIdx.x; i < NE;
         i += gridDim.x * blockDim.x)
        g_nbr[i] = is32 ? raw[i] : raw[2 * i];
}

// ---------------------------------------------------------------------------
// K1: T = x@wm_top (fp32); g_bxh[n] = fp16 record {B chunk, x chunk} per lane.
// Lane l holds B features (2l,2l+1): chunk = l>>1, pos = l&1.
//   B half2 slot = chunk*4 + pos ; x half2 slot = chunk*4 + 2 + pos.
// ---------------------------------------------------------------------------
__global__ __launch_bounds__(256, 2)
void k_gemm_tb(const float* __restrict__ x, const float* __restrict__ wm)
{
    __shared__ float2 sT[FDIM * 32];
    __shared__ float2 sB[FDIM * 32];
    __shared__ float  sx[8][8][FDIM];     // [warp][row][k]

    const int tid = threadIdx.x;
    const float2* wm2 = (const float2*)wm;
    for (int i = tid; i < FDIM * 32; i += blockDim.x) {
        sT[i] = wm2[i];
        sB[i] = wm2[FDIM * 32 + i];
    }
    __syncthreads();

    const int lane = tid & 31, wsub = tid >> 5;
    const int gw = blockIdx.x * 8 + wsub;
    const int nwarps = gridDim.x * 8;
    const float2* x2 = (const float2*)x;
    const int chunk = lane >> 1, pos = lane & 1;

    for (int c = gw; c < NN / 8; c += nwarps) {
        const int base = c * 8;
        #pragma unroll
        for (int r = 0; r < 8; r++)
            ((float2*)sx[wsub][r])[lane] = x2[(base + r) * 32 + lane];
        __syncwarp();

        unsigned long long tA[8], bA[8];
        #pragma unroll
        for (int r = 0; r < 8; r++) { tA[r] = 0ull; bA[r] = 0ull; }

        #pragma unroll 8
        for (int k = 0; k < FDIM; k++) {
            unsigned long long wt, wb;
            memcpy(&wt, &sT[k * 32 + lane], 8);
            memcpy(&wb, &sB[k * 32 + lane], 8);
            #pragma unroll
            for (int r = 0; r < 8; r++) {
                const unsigned long long xk = pack2(sx[wsub][r][k]);
                fma2(tA[r], xk, wt);
                fma2(bA[r], xk, wb);
            }
        }
        #pragma unroll
        for (int r = 0; r < 8; r++) {
            ((float2*)g_T)[(base + r) * 32 + lane] = unpack2(tA[r]);
            const float2 bP = unpack2(bA[r]);
            const float2 xP = ((float2*)sx[wsub][r])[lane];
            __half2* rec = (__half2*)&g_bxh[(base + r) * 16];
            rec[chunk * 4 + pos]     = __float22half2_rn(bP);
            rec[chunk * 4 + 2 + pos] = __float22half2_rn(xP);
        }
        __syncwarp();
    }
}

// ---------------------------------------------------------------------------
// K2: x_new[n] = x[n] + sum_d sigmoid(T[n]+B[j])*drop[n,d]*x[j]
// Half-warp per node, float4 lanes. One 16B fp16 gather per edge-lane
// (B+x combined record). Explicit 8-deep drop prefetch. fp16 x_new out.
// ---------------------------------------------------------------------------
__global__ __launch_bounds__(256, 2)
void k_edge(const float* __restrict__ x, const float* __restrict__ drop)
{
    const int tid  = threadIdx.x;
    const int lane = tid & 31;
    const int hl   = lane >> 4;          // which node of the pair
    const int fl   = lane & 15;          // float4 slot (features 4fl..4fl+3)
    const int gw   = blockIdx.x * 8 + (tid >> 5);
    const int nwarps = gridDim.x * 8;

    const float4* x4 = (const float4*)x;
    const float4* T4 = (const float4*)g_T;

    for (int c = gw; c < NN / 2; c += nwarps) {
        const int n = c * 2 + hl;
        const float4 t = T4[n * 16 + fl];
        float4 a = x4[n * 16 + fl];

        int js[DEG];
        {
            const int4* nb4 = (const int4*)(g_nbr + n * DEG);
            #pragma unroll
            for (int q = 0; q < 4; q++) *(int4*)&js[q * 4] = nb4[q];
        }
        const float4* dm = (const float4*)(drop + (size_t)n * DEG * FDIM);

        float4 mbuf[8];
        #pragma unroll
        for (int half = 0; half < 2; half++) {
            const int d0 = half * 8;
            #pragma unroll
            for (int q = 0; q < 8; q++)
                mbuf[q] = __ldcs(dm + (d0 + q) * 16 + fl);
            #pragma unroll
            for (int q = 0; q < 8; q++) {
                const int j = js[d0 + q];
                const uint4 v = g_bxh[j * 16 + fl];
                const __half2* hv = (const __half2*)&v;
                const float2 b01 = __half22float2(hv[0]);
                const float2 b23 = __half22float2(hv[1]);
                const float2 x01 = __half22float2(hv[2]);
                const float2 x23 = __half22float2(hv[3]);
                const float4 m = mbuf[q];
                a.x += sigmoid_fast(t.x + b01.x) * m.x * x01.x;
                a.y += sigmoid_fast(t.y + b01.y) * m.y * x01.y;
                a.z += sigmoid_fast(t.z + b23.x) * m.z * x23.x;
                a.w += sigmoid_fast(t.w + b23.y) * m.w * x23.y;
            }
        }
        uint2 st;
        *(__half2*)&st.x = __float22half2_rn(make_float2(a.x, a.y));
        *(__half2*)&st.y = __float22half2_rn(make_float2(a.z, a.w));
        g_xnh[n * 16 + fl] = st;
    }
}

// ---------------------------------------------------------------------------
// K34 (fused): agg[n] = sum_d adj[n,d]*x_new[nbr[n,d]] (fp16 gather, 8B/lane)
// staged into shared, then out = agg @ weight_0 + bias (8 rows/warp, f32x2).
// 3 CTAs/SM.
// ---------------------------------------------------------------------------
__global__ __launch_bounds__(256, 3)
void k_agg_gemm(const float* __restrict__ adj, const float* __restrict__ w0,
                const float* __restrict__ bias, float* __restrict__ out)
{
    __shared__ float2 sW[FDIM * 32];
    __shared__ float  sx[8][8][FDIM];

    const int tid = threadIdx.x;
    const float2* w02 = (const float2*)w0;
    for (int i = tid; i < FDIM * 32; i += blockDim.x) sW[i] = w02[i];
    __syncthreads();

    const int lane = tid & 31, wsub = tid >> 5;
    const int hl = lane >> 4, fl = lane & 15;
    const int gw = blockIdx.x * 8 + wsub;
    const int nwarps = gridDim.x * 8;

    const float2 bi = ((const float2*)bias)[lane];
    unsigned long long biP;
    memcpy(&biP, &bi, 8);

    for (int c = gw; c < NN / 8; c += nwarps) {
        const int base = c * 8;

        // Phase A: aggregate 8 nodes (2 per pass, half-warp each) into shared
        #pragma unroll
        for (int p = 0; p < 4; p++) {
            const int n = base + 2 * p + hl;
            float aj[DEG];
            int js[DEG];
            {
                const float4* a4 = (const float4*)(adj + (size_t)n * DEG);
                const int4* nb4 = (const int4*)(g_nbr + n * DEG);
                #pragma unroll
                for (int q = 0; q < 4; q++) {
                    *(float4*)&aj[q * 4] = __ldcs(a4 + q);
                    *(int4*)&js[q * 4]   = nb4[q];
                }
            }
            float4 acc = make_float4(0.f, 0.f, 0.f, 0.f);
            #pragma unroll
            for (int d = 0; d < DEG; d++) {
                const uint2 sv = g_xnh[js[d] * 16 + fl];
                const float2 s01 = __half22float2(*(const __half2*)&sv.x);
                const float2 s23 = __half22float2(*(const __half2*)&sv.y);
                acc.x += aj[d] * s01.x;  acc.y += aj[d] * s01.y;
                acc.z += aj[d] * s23.x;  acc.w += aj[d] * s23.y;
            }
            *(float4*)&sx[wsub][2 * p + hl][fl * 4] = acc;
        }
        __syncwarp();

        // Phase B: out rows = sx @ W0 + bias
        unsigned long long o[8];
        #pragma unroll
        for (int r = 0; r < 8; r++) o[r] = biP;

        #pragma unroll 8
        for (int k = 0; k < FDIM; k++) {
            unsigned long long wv;
            memcpy(&wv, &sW[k * 32 + lane], 8);
            #pragma unroll
            for (int r = 0; r < 8; r++)
                fma2(o[r], pack2(sx[wsub][r][k]), wv);
        }
        #pragma unroll
        for (int r = 0; r < 8; r++)
            ((float2*)out)[(base + r) * 32 + lane] = unpack2(o[r]);
        __syncwarp();
    }
}

// ---------------------------------------------------------------------------
extern "C" void kernel_launch(void* const* d_in, const int* in_sizes, int n_in,
                              void* d_out, int out_size)
{
    const float* x    = (const float*)d_in[0];
    const float* w0   = (const float*)d_in[1];
    const float* wm   = (const float*)d_in[2];
    const float* bias = (const float*)d_in[3];
    const float* adj  = (const float*)d_in[4];
    const float* drop = (const float*)d_in[5];
    const int*   nbrr = (const int*)d_in[6];
    float* out = (float*)d_out;

    k_detect  <<<64, 256>>>(nbrr);
    k_convert <<<148, 256>>>(nbrr);
    k_gemm_tb <<<296, 256>>>(x, wm);
    k_edge    <<<592, 256>>>(x, drop);
    k_agg_gemm<<<444, 256>>>(adj, w0, bias, out);
}